// round 15
// baseline (speedup 1.0000x reference)
#include <cuda_runtime.h>
#include <math.h>

#define T_TOK 16384
#define C_DIM 2048
#define E_NUM 64
#define GRID  128

__device__ float g_ctx[4 * C_DIM];
__device__ float g_imp[E_NUM];
__device__ float g_load[E_NUM];
__device__ int   g_sync;
__device__ int   g_done;

__device__ __forceinline__ void ffma2(unsigned long long& d,
                                      unsigned long long a,
                                      unsigned long long b)
{
    asm("fma.rn.f32x2 %0, %1, %2, %0;" : "+l"(d) : "l"(a), "l"(b));
}
__device__ __forceinline__ unsigned long long pack2(float v)
{
    unsigned long long r;
    unsigned int u = __float_as_uint(v);
    asm("mov.b64 %0, {%1, %1};" : "=l"(r) : "r"(u));
    return r;
}

#define OFF_XS  0
#define OFF_GS  32768
#define OFF_LOG 49152
#define OFF_IMP 82432
#define OFF_LD  82688
#define SMEMSZ  82944

// ---------------------------------------------------------------------------
// Fused kernel.  Phase 1: cooperative ctx, 1024 warps x 2 columns, with
// register-bounded load batching (wv[4][4], MLP=4) — fmaf order identical to
// the proven chain -> bitwise.  Grid spin barrier.  Phase 2: byte-identical
// R11 GEMM router + fused epilogue + last-CTA aux and counter reset.
// ---------------------------------------------------------------------------
__global__ void __launch_bounds__(256, 1) fused_kernel(const float* __restrict__ x,
                                                       const float* __restrict__ rc,
                                                       const float* __restrict__ ctx_w,
                                                       const float* __restrict__ gate_w,
                                                       float* __restrict__ out)
{
    extern __shared__ unsigned char smem[];
    float* xs2   = (float*)(smem + OFF_XS);
    float* gs2   = (float*)(smem + OFF_GS);
    float* sLog  = (float*)(smem + OFF_LOG);
    float* sImp  = (float*)(smem + OFF_IMP);
    int*   sLoad = (int*)(smem + OFF_LD);

    const int tid  = threadIdx.x;
    const int wid  = tid >> 5;
    const int lane = tid & 31;

    // ================= phase 1: ctx =================
    if (blockIdx.x == 0 && tid < 2 * E_NUM) {
        if (tid < E_NUM) g_imp[tid] = 0.f;
        else             g_load[tid - E_NUM] = 0.f;
    }
    {
        const int wg = blockIdx.x * 8 + wid;          // 0..1023
        const float4* q0p = (const float4*)(rc)             + lane;
        const float4* q1p = (const float4*)(rc +     C_DIM) + lane;
        const float4* q2p = (const float4*)(rc + 2 * C_DIM) + lane;
        const float4* q3p = (const float4*)(rc + 3 * C_DIM) + lane;
        #pragma unroll
        for (int cc = 0; cc < 2; cc++) {
            const int c = wg * 2 + cc;
            const float4* w4 = (const float4*)(ctx_w + (size_t)c * C_DIM) + lane;
            float a0 = 0.f, a1 = 0.f, a2 = 0.f, a3 = 0.f;
            #pragma unroll
            for (int jb = 0; jb < 4; jb++) {
                float wv[4][4];                       // only 16 live regs
                #pragma unroll
                for (int j = 0; j < 4; j++)
                    asm volatile("ld.global.nc.v4.f32 {%0,%1,%2,%3}, [%4];"
                                 : "=f"(wv[j][0]), "=f"(wv[j][1]),
                                   "=f"(wv[j][2]), "=f"(wv[j][3])
                                 : "l"(w4 + (jb * 4 + j) * 32));
                #pragma unroll
                for (int j = 0; j < 4; j++) {
                    const int jj = jb * 4 + j;
                    float4 q0 = q0p[jj * 32], q1 = q1p[jj * 32];
                    float4 q2 = q2p[jj * 32], q3 = q3p[jj * 32];
                    a0 = fmaf(wv[j][0], q0.x, fmaf(wv[j][1], q0.y, fmaf(wv[j][2], q0.z, fmaf(wv[j][3], q0.w, a0))));
                    a1 = fmaf(wv[j][0], q1.x, fmaf(wv[j][1], q1.y, fmaf(wv[j][2], q1.z, fmaf(wv[j][3], q1.w, a1))));
                    a2 = fmaf(wv[j][0], q2.x, fmaf(wv[j][1], q2.y, fmaf(wv[j][2], q2.z, fmaf(wv[j][3], q2.w, a2))));
                    a3 = fmaf(wv[j][0], q3.x, fmaf(wv[j][1], q3.y, fmaf(wv[j][2], q3.z, fmaf(wv[j][3], q3.w, a3))));
                }
            }
            #pragma unroll
            for (int o = 16; o; o >>= 1) {
                a0 += __shfl_down_sync(0xffffffffu, a0, o);
                a1 += __shfl_down_sync(0xffffffffu, a1, o);
                a2 += __shfl_down_sync(0xffffffffu, a2, o);
                a3 += __shfl_down_sync(0xffffffffu, a3, o);
            }
            if (lane == 0) {
                g_ctx[c]             = a0;
                g_ctx[C_DIM + c]     = a1;
                g_ctx[2 * C_DIM + c] = a2;
                g_ctx[3 * C_DIM + c] = a3;
            }
        }
    }
    // ---- grid-wide barrier (128 CTAs, all resident at 1 CTA/SM) ----
    __syncthreads();
    if (tid == 0) {
        __threadfence();
        atomicAdd(&g_sync, 1);
        while (atomicAdd(&g_sync, 0) < GRID) __nanosleep(64);
    }
    __syncthreads();

    // ================= phase 2: router (byte-identical to R11) =================
    const int token0 = blockIdx.x * 128;
    const int batch  = token0 >> 12;

    if (tid < E_NUM) { sImp[tid] = 0.f; sLoad[tid] = 0; }

    const int lt = tid >> 1;
    const int lh = (tid & 1) << 4;
    const int ge = tid >> 2;
    const int gk = (tid & 3) << 3;
    const float4* xp = (const float4*)(x      + (size_t)(token0 + lt) * C_DIM + lh);
    const float4* cp = (const float4*)(g_ctx  + (size_t)batch         * C_DIM + lh);
    const float4* gp = (const float4*)(gate_w + (size_t)ge            * C_DIM + gk);

    const int ti = (tid & 31) << 2;
    const int ej = (tid >> 5) << 3;

    unsigned long long acc2[4][4];
    #pragma unroll
    for (int a = 0; a < 4; a++)
        #pragma unroll
        for (int b = 0; b < 4; b++) acc2[a][b] = 0ull;

    float4 xr[4], cr[4], gr[2];
    #pragma unroll
    for (int j = 0; j < 4; j++) { xr[j] = xp[j]; cr[j] = cp[j]; }
    #pragma unroll
    for (int j = 0; j < 2; j++) gr[j] = gp[j];
    {
        float* xs = xs2;
        float* gs = gs2;
        #pragma unroll
        for (int j = 0; j < 4; j++)
            #pragma unroll
            for (int i = 0; i < 4; i++)
                xs[(lh + j * 4 + i) * 128 + lt] = ((const float*)&xr[j])[i] + ((const float*)&cr[j])[i];
        #pragma unroll
        for (int j = 0; j < 2; j++)
            #pragma unroll
            for (int i = 0; i < 4; i++)
                gs[(gk + j * 4 + i) * 64 + ge] = ((const float*)&gr[j])[i];
    }
    __syncthreads();

    for (int c = 0; c < 64; c++) {
        if (c < 63) {
            #pragma unroll
            for (int j = 0; j < 4; j++) {
                xr[j] = xp[(c + 1) * 8 + j];
                cr[j] = cp[(c + 1) * 8 + j];
            }
            #pragma unroll
            for (int j = 0; j < 2; j++) gr[j] = gp[(c + 1) * 8 + j];
        }
        const float* xs = xs2 + (c & 1) * (32 * 128);
        const float* gs = gs2 + (c & 1) * (32 * 64);
        #pragma unroll
        for (int kk = 0; kk < 32; kk++) {
            float4 xv = *(const float4*)&xs[kk * 128 + ti];
            ulonglong2 gA = *(const ulonglong2*)&gs[kk * 64 + ej];
            ulonglong2 gB = *(const ulonglong2*)&gs[kk * 64 + ej + 4];
            unsigned long long xq[4] = {pack2(xv.x), pack2(xv.y), pack2(xv.z), pack2(xv.w)};
            #pragma unroll
            for (int a = 0; a < 4; a++) {
                ffma2(acc2[a][0], xq[a], gA.x);
                ffma2(acc2[a][1], xq[a], gA.y);
                ffma2(acc2[a][2], xq[a], gB.x);
                ffma2(acc2[a][3], xq[a], gB.y);
            }
        }
        if (c < 63) {
            float* xsn = xs2 + ((c + 1) & 1) * (32 * 128);
            float* gsn = gs2 + ((c + 1) & 1) * (32 * 64);
            #pragma unroll
            for (int j = 0; j < 4; j++)
                #pragma unroll
                for (int i = 0; i < 4; i++)
                    xsn[(lh + j * 4 + i) * 128 + lt] = ((const float*)&xr[j])[i] + ((const float*)&cr[j])[i];
            #pragma unroll
            for (int j = 0; j < 2; j++)
                #pragma unroll
                for (int i = 0; i < 4; i++)
                    gsn[(gk + j * 4 + i) * 64 + ge] = ((const float*)&gr[j])[i];
        }
        __syncthreads();
    }

    #pragma unroll
    for (int a = 0; a < 4; a++)
        #pragma unroll
        for (int b = 0; b < 4; b++) {
            unsigned int lo, hi;
            asm("mov.b64 {%0, %1}, %2;" : "=r"(lo), "=r"(hi) : "l"(acc2[a][b]));
            sLog[(ti + a) * 65 + ej + 2 * b]     = __uint_as_float(lo);
            sLog[(ti + a) * 65 + ej + 2 * b + 1] = __uint_as_float(hi);
        }
    __syncthreads();

    if (tid < 128) {
        const int tok = token0 + tid;
        float* row = &sLog[tid * 65];

        float v0 = -1e30f, v1 = -1e30f;
        int   i0 = 0, i1 = 0;
        for (int e = 0; e < E_NUM; e++) {
            float l = row[e];
            if (l > v0)      { v1 = v0; i1 = i0; v0 = l; i0 = e; }
            else if (l > v1) { v1 = l; i1 = e; }
        }
        float sum = 0.f;
        for (int e = 0; e < E_NUM; e++) {
            float p = expf(row[e] - v0);
            row[e] = p;
            sum += p;
        }
        float inv = 1.0f / sum;
        int ln = tid & 31;
        for (int e = 0; e < E_NUM; e++) {
            int ee = (e + ln) & 63;
            atomicAdd(&sImp[ee], row[ee] * inv);
        }
        atomicAdd(&sLoad[i0], 1);
        atomicAdd(&sLoad[i1], 1);

        float e1 = expf(v1 - v0);
        float w0 = 1.0f / (1.0f + e1);
        out[(size_t)tok * 2 + 0] = (float)i0;
        out[(size_t)tok * 2 + 1] = (float)i1;
        out[2 * T_TOK + (size_t)tok * 2 + 0] = w0;
        out[2 * T_TOK + (size_t)tok * 2 + 1] = e1 * w0;
    }
    __syncthreads();
    if (tid < E_NUM) {
        atomicAdd(&g_imp[tid],  sImp[tid]);
        atomicAdd(&g_load[tid], (float)sLoad[tid]);
    }

    // ---- last CTA: aux_loss + counter reset for next graph replay ----
    __shared__ int sLast;
    __syncthreads();
    if (tid == 0) {
        __threadfence();
        sLast = (atomicAdd(&g_done, 1) == GRID - 1) ? 1 : 0;
    }
    __syncthreads();
    if (sLast && tid == 0) {
        float a = 0.f;
        for (int e = 0; e < E_NUM; e++) {
            float im = atomicAdd(&g_imp[e],  0.f);
            float ld = atomicAdd(&g_load[e], 0.f);
            a += im * ld;
        }
        out[4 * T_TOK] = (float)E_NUM * a / ((float)T_TOK * (float)T_TOK);
        g_sync = 0;
        g_done = 0;
    }
}

// ---------------------------------------------------------------------------
extern "C" void kernel_launch(void* const* d_in, const int* in_sizes, int n_in,
                              void* d_out, int out_size)
{
    const float* x      = (const float*)d_in[0];
    const float* rc     = (const float*)d_in[1];
    const float* gate_w = (const float*)d_in[2];
    const float* ctx_w  = (const float*)d_in[3];
    float* out = (float*)d_out;

    cudaFuncSetAttribute(fused_kernel, cudaFuncAttributeMaxDynamicSharedMemorySize, SMEMSZ);

    fused_kernel<<<GRID, 256, SMEMSZ>>>(x, rc, ctx_w, gate_w, out);
}

// round 16
// speedup vs baseline: 1.0517x; 1.0517x over previous
#include <cuda_runtime.h>
#include <math.h>

#define T_TOK 16384
#define C_DIM 2048
#define E_NUM 64

__device__ float g_ctx[4 * C_DIM];
__device__ float g_imp[E_NUM];
__device__ float g_load[E_NUM];
__device__ int   g_done;

__device__ __forceinline__ void ffma2(unsigned long long& d,
                                      unsigned long long a,
                                      unsigned long long b)
{
    asm("fma.rn.f32x2 %0, %1, %2, %0;" : "+l"(d) : "l"(a), "l"(b));
}
__device__ __forceinline__ unsigned long long pack2(float v)
{
    unsigned long long r;
    unsigned int u = __float_as_uint(v);
    asm("mov.b64 %0, {%1, %1};" : "=l"(r) : "r"(u));
    return r;
}

// ---------------------------------------------------------------------------
// ctx[b][c] = sum_k rc[b][k] * ctx_w[c][k] — bitwise-R3 fmaf/shfl chain.
// vs R11: pinned DRAM loads in TWO batches of 8 (wv[8][4] = 32 regs, fits
// without spills; R10/R11's 16-deep batch forced ptxas to spill between the
// volatile loads, serializing them).  Batch 1 issues before batch 0 is
// consumed, hiding its latency under the first 8 fmaf groups.
// ---------------------------------------------------------------------------
__global__ void __launch_bounds__(256) ctx_kernel(const float* __restrict__ rc,
                                                  const float* __restrict__ ctx_w)
{
    __shared__ float src[4 * C_DIM];           // 32 KB staged rc

    const int c    = blockIdx.x * 8 + (threadIdx.x >> 5);
    const int lane = threadIdx.x & 31;
    const float4* w4 = (const float4*)(ctx_w + (size_t)c * C_DIM) + lane;

    // batch 0: 8 pinned in-flight DRAM loads (issued before anything else)
    float wv0[8][4];
    #pragma unroll
    for (int j = 0; j < 8; j++)
        asm volatile("ld.global.nc.v4.f32 {%0,%1,%2,%3}, [%4];"
                     : "=f"(wv0[j][0]), "=f"(wv0[j][1]), "=f"(wv0[j][2]), "=f"(wv0[j][3])
                     : "l"(w4 + j * 32));

    if (blockIdx.x == 0 && threadIdx.x < 2 * E_NUM) {
        if (threadIdx.x < E_NUM) g_imp[threadIdx.x] = 0.f;
        else                     g_load[threadIdx.x - E_NUM] = 0.f;
        if (threadIdx.x == 0)    g_done = 0;
    }
    // stage rc -> smem (overlaps batch-0 latency)
    {
        const float4* s = (const float4*)rc;
        float4*       d = (float4*)src;
        #pragma unroll
        for (int j = 0; j < 8; j++) d[threadIdx.x + j * 256] = s[threadIdx.x + j * 256];
    }
    __syncthreads();

    // batch 1: next 8 pinned loads (latency hidden under batch-0 compute)
    float wv1[8][4];
    #pragma unroll
    for (int j = 0; j < 8; j++)
        asm volatile("ld.global.nc.v4.f32 {%0,%1,%2,%3}, [%4];"
                     : "=f"(wv1[j][0]), "=f"(wv1[j][1]), "=f"(wv1[j][2]), "=f"(wv1[j][3])
                     : "l"(w4 + (8 + j) * 32));

    const float4* q0p = (const float4*)(src)             + lane;
    const float4* q1p = (const float4*)(src +     C_DIM) + lane;
    const float4* q2p = (const float4*)(src + 2 * C_DIM) + lane;
    const float4* q3p = (const float4*)(src + 3 * C_DIM) + lane;

    float a0 = 0.f, a1 = 0.f, a2 = 0.f, a3 = 0.f;
    #pragma unroll
    for (int j = 0; j < 8; j++) {
        float4 q0 = q0p[j * 32], q1 = q1p[j * 32];
        float4 q2 = q2p[j * 32], q3 = q3p[j * 32];
        a0 = fmaf(wv0[j][0], q0.x, fmaf(wv0[j][1], q0.y, fmaf(wv0[j][2], q0.z, fmaf(wv0[j][3], q0.w, a0))));
        a1 = fmaf(wv0[j][0], q1.x, fmaf(wv0[j][1], q1.y, fmaf(wv0[j][2], q1.z, fmaf(wv0[j][3], q1.w, a1))));
        a2 = fmaf(wv0[j][0], q2.x, fmaf(wv0[j][1], q2.y, fmaf(wv0[j][2], q2.z, fmaf(wv0[j][3], q2.w, a2))));
        a3 = fmaf(wv0[j][0], q3.x, fmaf(wv0[j][1], q3.y, fmaf(wv0[j][2], q3.z, fmaf(wv0[j][3], q3.w, a3))));
    }
    #pragma unroll
    for (int j = 0; j < 8; j++) {
        const int jj = 8 + j;
        float4 q0 = q0p[jj * 32], q1 = q1p[jj * 32];
        float4 q2 = q2p[jj * 32], q3 = q3p[jj * 32];
        a0 = fmaf(wv1[j][0], q0.x, fmaf(wv1[j][1], q0.y, fmaf(wv1[j][2], q0.z, fmaf(wv1[j][3], q0.w, a0))));
        a1 = fmaf(wv1[j][0], q1.x, fmaf(wv1[j][1], q1.y, fmaf(wv1[j][2], q1.z, fmaf(wv1[j][3], q1.w, a1))));
        a2 = fmaf(wv1[j][0], q2.x, fmaf(wv1[j][1], q2.y, fmaf(wv1[j][2], q2.z, fmaf(wv1[j][3], q2.w, a2))));
        a3 = fmaf(wv1[j][0], q3.x, fmaf(wv1[j][1], q3.y, fmaf(wv1[j][2], q3.z, fmaf(wv1[j][3], q3.w, a3))));
    }
    #pragma unroll
    for (int o = 16; o; o >>= 1) {
        a0 += __shfl_down_sync(0xffffffffu, a0, o);
        a1 += __shfl_down_sync(0xffffffffu, a1, o);
        a2 += __shfl_down_sync(0xffffffffu, a2, o);
        a3 += __shfl_down_sync(0xffffffffu, a3, o);
    }
    if (lane == 0) {
        g_ctx[c]             = a0;
        g_ctx[C_DIM + c]     = a1;
        g_ctx[2 * C_DIM + c] = a2;
        g_ctx[3 * C_DIM + c] = a3;
    }
}

// ---------------------------------------------------------------------------
// Router — byte-identical to the 123.7 µs R11 kernel (bitwise-R3 output),
// with the fused last-CTA aux_loss tail.
// ---------------------------------------------------------------------------
#define OFF_XS  0
#define OFF_GS  32768
#define OFF_LOG 49152
#define OFF_IMP 82432
#define OFF_LD  82688
#define SMEMSZ  82944

__global__ void __launch_bounds__(256, 1) router_kernel(const float* __restrict__ x,
                                                        const float* __restrict__ gate_w,
                                                        float* __restrict__ out)
{
    extern __shared__ unsigned char smem[];
    float* xs2   = (float*)(smem + OFF_XS);
    float* gs2   = (float*)(smem + OFF_GS);
    float* sLog  = (float*)(smem + OFF_LOG);
    float* sImp  = (float*)(smem + OFF_IMP);
    int*   sLoad = (int*)(smem + OFF_LD);

    const int tid    = threadIdx.x;
    const int token0 = blockIdx.x * 128;
    const int batch  = token0 >> 12;

    if (tid < E_NUM) { sImp[tid] = 0.f; sLoad[tid] = 0; }

    const int lt = tid >> 1;
    const int lh = (tid & 1) << 4;
    const int ge = tid >> 2;
    const int gk = (tid & 3) << 3;
    const float4* xp = (const float4*)(x      + (size_t)(token0 + lt) * C_DIM + lh);
    const float4* cp = (const float4*)(g_ctx  + (size_t)batch         * C_DIM + lh);
    const float4* gp = (const float4*)(gate_w + (size_t)ge            * C_DIM + gk);

    const int ti = (tid & 31) << 2;
    const int ej = (tid >> 5) << 3;

    unsigned long long acc2[4][4];
    #pragma unroll
    for (int a = 0; a < 4; a++)
        #pragma unroll
        for (int b = 0; b < 4; b++) acc2[a][b] = 0ull;

    float4 xr[4], cr[4], gr[2];
    #pragma unroll
    for (int j = 0; j < 4; j++) { xr[j] = xp[j]; cr[j] = cp[j]; }
    #pragma unroll
    for (int j = 0; j < 2; j++) gr[j] = gp[j];
    {
        float* xs = xs2;
        float* gs = gs2;
        #pragma unroll
        for (int j = 0; j < 4; j++)
            #pragma unroll
            for (int i = 0; i < 4; i++)
                xs[(lh + j * 4 + i) * 128 + lt] = ((const float*)&xr[j])[i] + ((const float*)&cr[j])[i];
        #pragma unroll
        for (int j = 0; j < 2; j++)
            #pragma unroll
            for (int i = 0; i < 4; i++)
                gs[(gk + j * 4 + i) * 64 + ge] = ((const float*)&gr[j])[i];
    }
    __syncthreads();

    for (int c = 0; c < 64; c++) {
        if (c < 63) {
            #pragma unroll
            for (int j = 0; j < 4; j++) {
                xr[j] = xp[(c + 1) * 8 + j];
                cr[j] = cp[(c + 1) * 8 + j];
            }
            #pragma unroll
            for (int j = 0; j < 2; j++) gr[j] = gp[(c + 1) * 8 + j];
        }
        const float* xs = xs2 + (c & 1) * (32 * 128);
        const float* gs = gs2 + (c & 1) * (32 * 64);
        #pragma unroll
        for (int kk = 0; kk < 32; kk++) {
            float4 xv = *(const float4*)&xs[kk * 128 + ti];
            ulonglong2 gA = *(const ulonglong2*)&gs[kk * 64 + ej];
            ulonglong2 gB = *(const ulonglong2*)&gs[kk * 64 + ej + 4];
            unsigned long long xq[4] = {pack2(xv.x), pack2(xv.y), pack2(xv.z), pack2(xv.w)};
            #pragma unroll
            for (int a = 0; a < 4; a++) {
                ffma2(acc2[a][0], xq[a], gA.x);
                ffma2(acc2[a][1], xq[a], gA.y);
                ffma2(acc2[a][2], xq[a], gB.x);
                ffma2(acc2[a][3], xq[a], gB.y);
            }
        }
        if (c < 63) {
            float* xsn = xs2 + ((c + 1) & 1) * (32 * 128);
            float* gsn = gs2 + ((c + 1) & 1) * (32 * 64);
            #pragma unroll
            for (int j = 0; j < 4; j++)
                #pragma unroll
                for (int i = 0; i < 4; i++)
                    xsn[(lh + j * 4 + i) * 128 + lt] = ((const float*)&xr[j])[i] + ((const float*)&cr[j])[i];
            #pragma unroll
            for (int j = 0; j < 2; j++)
                #pragma unroll
                for (int i = 0; i < 4; i++)
                    gsn[(gk + j * 4 + i) * 64 + ge] = ((const float*)&gr[j])[i];
        }
        __syncthreads();
    }

    #pragma unroll
    for (int a = 0; a < 4; a++)
        #pragma unroll
        for (int b = 0; b < 4; b++) {
            unsigned int lo, hi;
            asm("mov.b64 {%0, %1}, %2;" : "=r"(lo), "=r"(hi) : "l"(acc2[a][b]));
            sLog[(ti + a) * 65 + ej + 2 * b]     = __uint_as_float(lo);
            sLog[(ti + a) * 65 + ej + 2 * b + 1] = __uint_as_float(hi);
        }
    __syncthreads();

    if (tid < 128) {
        const int tok = token0 + tid;
        float* row = &sLog[tid * 65];

        float v0 = -1e30f, v1 = -1e30f;
        int   i0 = 0, i1 = 0;
        for (int e = 0; e < E_NUM; e++) {
            float l = row[e];
            if (l > v0)      { v1 = v0; i1 = i0; v0 = l; i0 = e; }
            else if (l > v1) { v1 = l; i1 = e; }
        }
        float sum = 0.f;
        for (int e = 0; e < E_NUM; e++) {
            float p = expf(row[e] - v0);
            row[e] = p;
            sum += p;
        }
        float inv = 1.0f / sum;
        int lane = tid & 31;
        for (int e = 0; e < E_NUM; e++) {
            int ee = (e + lane) & 63;
            atomicAdd(&sImp[ee], row[ee] * inv);
        }
        atomicAdd(&sLoad[i0], 1);
        atomicAdd(&sLoad[i1], 1);

        float e1 = expf(v1 - v0);
        float w0 = 1.0f / (1.0f + e1);
        out[(size_t)tok * 2 + 0] = (float)i0;
        out[(size_t)tok * 2 + 1] = (float)i1;
        out[2 * T_TOK + (size_t)tok * 2 + 0] = w0;
        out[2 * T_TOK + (size_t)tok * 2 + 1] = e1 * w0;
    }
    __syncthreads();
    if (tid < E_NUM) {
        atomicAdd(&g_imp[tid],  sImp[tid]);
        atomicAdd(&g_load[tid], (float)sLoad[tid]);
    }

    __shared__ int sLast;
    __syncthreads();
    if (tid == 0) {
        __threadfence();
        sLast = (atomicAdd(&g_done, 1) == (int)gridDim.x - 1) ? 1 : 0;
    }
    __syncthreads();
    if (sLast && tid == 0) {
        float a = 0.f;
        for (int e = 0; e < E_NUM; e++) {
            float im = atomicAdd(&g_imp[e],  0.f);
            float ld = atomicAdd(&g_load[e], 0.f);
            a += im * ld;
        }
        out[4 * T_TOK] = (float)E_NUM * a / ((float)T_TOK * (float)T_TOK);
    }
}

// ---------------------------------------------------------------------------
extern "C" void kernel_launch(void* const* d_in, const int* in_sizes, int n_in,
                              void* d_out, int out_size)
{
    const float* x      = (const float*)d_in[0];
    const float* rc     = (const float*)d_in[1];
    const float* gate_w = (const float*)d_in[2];
    const float* ctx_w  = (const float*)d_in[3];
    float* out = (float*)d_out;

    cudaFuncSetAttribute(router_kernel, cudaFuncAttributeMaxDynamicSharedMemorySize, SMEMSZ);

    ctx_kernel   <<<256, 256>>>(rc, ctx_w);
    router_kernel<<<128, 256, SMEMSZ>>>(x, gate_w, out);
}